// round 17
// baseline (speedup 1.0000x reference)
#include <cuda_runtime.h>
#include <cuda_fp16.h>
#include <mma.h>
#include <cstdint>

using namespace nvcuda;

// GCN: out = GCNConv2( relu(GCNConv1(x)) )
// Hs = dinv ⊙ (X W1) via fp16 tensor cores (fp32 accum), fp16 messages;
// agg1: warp/node, 2 parallel edge-halves (uint4/lane) + shfl reduce;
// gemm2: Hs2 = dinv*(x1 @ W2);  agg2: warp/node, 4 edge-quarters + shfl reduce.
// CSR build: hist captures per-edge rank (atomicAdd return), fill is atomic-free.

#define N_NODES 100000
#define N_EDGES 1600000
#define EMB 128
#define HID 128
#define RPR 64
#define SCAN_BLOCKS 391   // ceil(100000/256)

// ---------------- scratch (device globals, allocation-free) ----------------
__device__ float  g_dinv[N_NODES];
__device__ __half g_Hs [(long long)N_NODES * HID];   // layer1 scaled hidden (fp16)
__device__ __half g_X1h[(long long)N_NODES * HID];   // relu(conv1) output (fp16)
__device__ __half g_Hs2[(long long)N_NODES * RPR];   // layer2 scaled hidden (fp16)
__device__ int    g_cnt[N_NODES];
__device__ int    g_rowptr[N_NODES];                  // start; end = start + cnt
__device__ int    g_rank[N_EDGES];                    // per-edge rank within dst bucket
__device__ int    g_total;
__device__ int    g_adj[N_EDGES];

// ---------------- helpers ----------------
__device__ __forceinline__ unsigned int h2u(float a, float b) {
    __half2 h = __floats2half2_rn(a, b);
    return *reinterpret_cast<unsigned int*>(&h);
}
__device__ __forceinline__ float2 u2f(unsigned int u) {
    __half2 h = *reinterpret_cast<__half2*>(&u);
    return __half22float2(h);
}
// accumulate 8 halfs (uint4) into 8 fp32 accumulators
__device__ __forceinline__ void acc8(float* a, uint4 v) {
    float2 p0 = u2f(v.x), p1 = u2f(v.y), p2 = u2f(v.z), p3 = u2f(v.w);
    a[0] += p0.x; a[1] += p0.y; a[2] += p1.x; a[3] += p1.y;
    a[4] += p2.x; a[5] += p2.y; a[6] += p3.x; a[7] += p3.y;
}

// ---------------- CSR build + degree ----------------
__global__ void k_zero() {
    int i = blockIdx.x * blockDim.x + threadIdx.x;
    if (i < N_NODES) g_cnt[i] = 0;
    if (i == 0) g_total = 0;
}

// histogram + capture per-edge rank (the atomicAdd return value)
__global__ void k_hist(const int* __restrict__ dst) {
    int stride = gridDim.x * blockDim.x;
    const int4* d4 = (const int4*)dst;
    int4* r4 = (int4*)g_rank;
    for (int e = blockIdx.x * blockDim.x + threadIdx.x; e < N_EDGES / 4; e += stride) {
        int4 d = __ldg(d4 + e);
        int4 r;
        r.x = atomicAdd(&g_cnt[d.x], 1);
        r.y = atomicAdd(&g_cnt[d.y], 1);
        r.z = atomicAdd(&g_cnt[d.z], 1);
        r.w = atomicAdd(&g_cnt[d.w], 1);
        r4[e] = r;
    }
}

// single-kernel scan: block prefix sum + atomic base (rowptr need not be
// globally monotonic; agg uses end = rowptr + cnt)
__global__ void k_scan() {
    __shared__ int sh[256];
    __shared__ int base;
    int t = threadIdx.x;
    int i = blockIdx.x * 256 + t;
    int v = (i < N_NODES) ? g_cnt[i] : 0;
    sh[t] = v;
    __syncthreads();
    for (int off = 1; off < 256; off <<= 1) {
        int add = 0;
        if (t >= off) add = sh[t - off];
        __syncthreads();
        sh[t] += add;
        __syncthreads();
    }
    if (t == 255) base = atomicAdd(&g_total, sh[255]);
    __syncthreads();
    int excl = base + sh[t] - v;
    if (i < N_NODES) {
        g_rowptr[i] = excl;
        g_dinv[i]   = rsqrtf(1.0f + (float)v);   // +1 for self loop
    }
}

// atomic-free fill: slot = rowptr[dst] + rank (each slot written exactly once)
__global__ void k_fill(const int* __restrict__ src, const int* __restrict__ dst) {
    int stride = gridDim.x * blockDim.x;
    const int4* s4 = (const int4*)src;
    const int4* d4 = (const int4*)dst;
    const int4* r4 = (const int4*)g_rank;
    for (int e = blockIdx.x * blockDim.x + threadIdx.x; e < N_EDGES / 4; e += stride) {
        int4 s = __ldg(s4 + e);
        int4 d = __ldg(d4 + e);
        int4 r = __ldg(r4 + e);
        g_adj[__ldg(&g_rowptr[d.x]) + r.x] = s.x;
        g_adj[__ldg(&g_rowptr[d.y]) + r.y] = s.y;
        g_adj[__ldg(&g_rowptr[d.z]) + r.z] = s.z;
        g_adj[__ldg(&g_rowptr[d.w]) + r.w] = s.w;
    }
}

// ---------------- layer-1 GEMM (tensor cores): Hs = dinv * (x @ W1), fp16 out ---
#define LDA1 136
#define LDC1 132
__global__ __launch_bounds__(256)
void k_gemm1_tc(const float* __restrict__ x, const float* __restrict__ W1) {
    extern __shared__ char dynsmem[];
    __half* A_h = (__half*)dynsmem;                 // [128][136]
    __half* B_h = A_h + 128 * LDA1;                 // [128][136]
    float*  C_f = (float*)dynsmem;                  // [128][132] (reuse after mma)

    const int tid  = threadIdx.x;
    const int warp = tid >> 5;
    const int rowBase = blockIdx.x * 128;

    // fill B: W1 fp32 -> fp16 (128x128), pairs
    for (int idx = tid; idx < 128 * 64; idx += 256) {
        int k = idx >> 6, n2 = idx & 63;
        float2 w = *(const float2*)&W1[k * HID + n2 * 2];
        *(unsigned int*)&B_h[k * LDA1 + n2 * 2] = h2u(w.x, w.y);
    }
    // fill A: x tile fp32 -> fp16, zero-pad invalid rows
    for (int idx = tid; idx < 128 * 32; idx += 256) {
        int r = idx >> 5, q4 = idx & 31;
        int gr = rowBase + r;
        unsigned int p0 = 0, p1 = 0;
        if (gr < N_NODES) {
            float4 v = *(const float4*)&x[(size_t)gr * EMB + q4 * 4];
            p0 = h2u(v.x, v.y);
            p1 = h2u(v.z, v.w);
        }
        *(unsigned int*)&A_h[r * LDA1 + q4 * 4]     = p0;
        *(unsigned int*)&A_h[r * LDA1 + q4 * 4 + 2] = p1;
    }
    __syncthreads();

    wmma::fragment<wmma::accumulator, 16, 16, 16, float> acc[8];
#pragma unroll
    for (int n = 0; n < 8; n++) wmma::fill_fragment(acc[n], 0.0f);

#pragma unroll
    for (int k = 0; k < 8; k++) {
        wmma::fragment<wmma::matrix_a, 16, 16, 16, __half, wmma::row_major> a;
        wmma::load_matrix_sync(a, &A_h[warp * 16 * LDA1 + k * 16], LDA1);
#pragma unroll
        for (int n = 0; n < 8; n++) {
            wmma::fragment<wmma::matrix_b, 16, 16, 16, __half, wmma::row_major> b;
            wmma::load_matrix_sync(b, &B_h[k * 16 * LDA1 + n * 16], LDA1);
            wmma::mma_sync(acc[n], a, b, acc[n]);
        }
    }
    __syncthreads();   // done reading A/B smem; reuse as C staging

#pragma unroll
    for (int n = 0; n < 8; n++)
        wmma::store_matrix_sync(&C_f[warp * 16 * LDC1 + n * 16], acc[n], LDC1,
                                wmma::mem_row_major);
    __syncthreads();

    // epilogue: scale by dinv, convert fp16, write. 2 threads/row, 64 cols each.
    {
        int r = tid >> 1, seg = tid & 1;
        int gr = rowBase + r;
        if (gr < N_NODES) {
            float di = __ldg(&g_dinv[gr]);
            const float* cr = &C_f[r * LDC1 + seg * 64];
            __half* hp = g_Hs + (size_t)gr * HID + seg * 64;
#pragma unroll
            for (int q = 0; q < 8; q++) {
                float4 v0 = *(const float4*)(cr + q * 8);
                float4 v1 = *(const float4*)(cr + q * 8 + 4);
                uint4 o;
                o.x = h2u(v0.x * di, v0.y * di);
                o.y = h2u(v0.z * di, v0.w * di);
                o.z = h2u(v1.x * di, v1.y * di);
                o.w = h2u(v1.z * di, v1.w * di);
                *(uint4*)(hp + q * 8) = o;
            }
        }
    }
}

// ---------------- layer-1 aggregate + relu + bias -> x1 (fp16) ----------------
// WARP per node; 2 edge-halves of 16 lanes (uint4/lane); shfl-xor(16) reduce
__global__ void k_agg1(const float* __restrict__ b1) {
    int gw = (blockIdx.x * blockDim.x + threadIdx.x) >> 5;   // node
    if (gw >= N_NODES) return;
    const int lane = threadIdx.x & 31;
    const int h = lane >> 4;        // edge-half 0/1
    const int l = lane & 15;        // cols l*8..+7
    const uint4* hs = (const uint4*)g_Hs;     // row stride = 16 uint4

    float acc[8] = {0, 0, 0, 0, 0, 0, 0, 0};
    if (h == 0) {
        uint4 sv = __ldg(hs + (size_t)gw * 16 + l);   // self loop (half 0 only)
        acc8(acc, sv);
    }

    int beg = __ldg(&g_rowptr[gw]);
    int end = beg + __ldg(&g_cnt[gw]);
    int i = beg + h;                 // this half's edges: beg+h, beg+h+2, ...
    for (; i + 2 < end; i += 4) {    // unroll 2: edges i and i+2
        int s0 = __ldg(g_adj + i);
        int s1 = __ldg(g_adj + i + 2);
        uint4 v0 = __ldg(hs + (size_t)s0 * 16 + l);
        uint4 v1 = __ldg(hs + (size_t)s1 * 16 + l);
        acc8(acc, v0); acc8(acc, v1);
    }
    if (i < end) {
        int s = __ldg(g_adj + i);
        uint4 v = __ldg(hs + (size_t)s * 16 + l);
        acc8(acc, v);
    }

    // merge halves
#pragma unroll
    for (int k = 0; k < 8; k++)
        acc[k] += __shfl_xor_sync(0xffffffffu, acc[k], 16);

    if (h == 0) {
        float di = __ldg(&g_dinv[gw]);
        float4 bv0 = __ldg((const float4*)b1 + l * 2);
        float4 bv1 = __ldg((const float4*)b1 + l * 2 + 1);
        float r0 = fmaxf(fmaf(di, acc[0], bv0.x), 0.0f);
        float r1 = fmaxf(fmaf(di, acc[1], bv0.y), 0.0f);
        float r2 = fmaxf(fmaf(di, acc[2], bv0.z), 0.0f);
        float r3 = fmaxf(fmaf(di, acc[3], bv0.w), 0.0f);
        float r4 = fmaxf(fmaf(di, acc[4], bv1.x), 0.0f);
        float r5 = fmaxf(fmaf(di, acc[5], bv1.y), 0.0f);
        float r6 = fmaxf(fmaf(di, acc[6], bv1.z), 0.0f);
        float r7 = fmaxf(fmaf(di, acc[7], bv1.w), 0.0f);
        uint4 o;
        o.x = h2u(r0, r1);
        o.y = h2u(r2, r3);
        o.z = h2u(r4, r5);
        o.w = h2u(r6, r7);
        ((uint4*)g_X1h)[(size_t)gw * 16 + l] = o;
    }
}

// ---------------- layer-2 GEMM (tensor cores): Hs2 = dinv * (x1 @ W2), fp16 out
#define LDA2 136
#define LDB2 72
#define LDC2 68
__global__ __launch_bounds__(256)
void k_gemm2_tc(const float* __restrict__ W2) {
    extern __shared__ char dynsmem[];
    __half* A_h = (__half*)dynsmem;                 // [128][136]
    __half* B_h = A_h + 128 * LDA2;                 // [128][72]
    float*  C_f = (float*)dynsmem;                  // [128][68] (reuse)

    const int tid  = threadIdx.x;
    const int warp = tid >> 5;
    const int rowBase = blockIdx.x * 128;

    // fill B: W2 fp32 -> fp16 (128x64)
    for (int idx = tid; idx < 128 * 32; idx += 256) {
        int k = idx >> 5, n2 = idx & 31;
        float2 w = *(const float2*)&W2[k * RPR + n2 * 2];
        *(unsigned int*)&B_h[k * LDB2 + n2 * 2] = h2u(w.x, w.y);
    }
    // fill A: X1h fp16 direct copy (uint4 = 8 halfs)
    for (int idx = tid; idx < 128 * 16; idx += 256) {
        int r = idx >> 4, q = idx & 15;
        int gr = rowBase + r;
        uint4 v = make_uint4(0, 0, 0, 0);
        if (gr < N_NODES)
            v = *(const uint4*)&g_X1h[(size_t)gr * HID + q * 8];
        *(uint4*)&A_h[r * LDA2 + q * 8] = v;
    }
    __syncthreads();

    wmma::fragment<wmma::accumulator, 16, 16, 16, float> acc[4];
#pragma unroll
    for (int n = 0; n < 4; n++) wmma::fill_fragment(acc[n], 0.0f);

#pragma unroll
    for (int k = 0; k < 8; k++) {
        wmma::fragment<wmma::matrix_a, 16, 16, 16, __half, wmma::row_major> a;
        wmma::load_matrix_sync(a, &A_h[warp * 16 * LDA2 + k * 16], LDA2);
#pragma unroll
        for (int n = 0; n < 4; n++) {
            wmma::fragment<wmma::matrix_b, 16, 16, 16, __half, wmma::row_major> b;
            wmma::load_matrix_sync(b, &B_h[k * 16 * LDB2 + n * 16], LDB2);
            wmma::mma_sync(acc[n], a, b, acc[n]);
        }
    }
    __syncthreads();

#pragma unroll
    for (int n = 0; n < 4; n++)
        wmma::store_matrix_sync(&C_f[warp * 16 * LDC2 + n * 16], acc[n], LDC2,
                                wmma::mem_row_major);
    __syncthreads();

    // epilogue: 2 threads/row, 32 cols each
    {
        int r = tid >> 1, seg = tid & 1;
        int gr = rowBase + r;
        if (gr < N_NODES) {
            float di = __ldg(&g_dinv[gr]);
            const float* cr = &C_f[r * LDC2 + seg * 32];
            __half* hp = g_Hs2 + (size_t)gr * RPR + seg * 32;
#pragma unroll
            for (int q = 0; q < 4; q++) {
                float4 v0 = *(const float4*)(cr + q * 8);
                float4 v1 = *(const float4*)(cr + q * 8 + 4);
                uint4 o;
                o.x = h2u(v0.x * di, v0.y * di);
                o.y = h2u(v0.z * di, v0.w * di);
                o.z = h2u(v1.x * di, v1.y * di);
                o.w = h2u(v1.z * di, v1.w * di);
                *(uint4*)(hp + q * 8) = o;
            }
        }
    }
}

// ---------------- layer-2 aggregate + bias -> out ----------------
// WARP per node; 4 edge-quarters of 8 lanes (uint4/lane); butterfly reduce
__global__ void k_agg2(const float* __restrict__ b2, float* __restrict__ out) {
    int gh = (blockIdx.x * blockDim.x + threadIdx.x) >> 5;   // node
    if (gh >= N_NODES) return;
    const int lane = threadIdx.x & 31;
    const int q = lane >> 3;        // edge-quarter 0..3
    const int l = lane & 7;         // cols l*8..+7
    const uint4* hs = (const uint4*)g_Hs2;    // row stride = 8 uint4

    float acc[8] = {0, 0, 0, 0, 0, 0, 0, 0};
    if (q == 0) {
        uint4 sv = __ldg(hs + (size_t)gh * 8 + l);   // self loop (quarter 0 only)
        acc8(acc, sv);
    }

    int beg = __ldg(&g_rowptr[gh]);
    int end = beg + __ldg(&g_cnt[gh]);
    int i = beg + q;                 // this quarter's edges: beg+q, beg+q+4, ...
    for (; i + 4 < end; i += 8) {    // unroll 2: edges i and i+4
        int s0 = __ldg(g_adj + i);
        int s1 = __ldg(g_adj + i + 4);
        uint4 v0 = __ldg(hs + (size_t)s0 * 8 + l);
        uint4 v1 = __ldg(hs + (size_t)s1 * 8 + l);
        acc8(acc, v0); acc8(acc, v1);
    }
    if (i < end) {
        int s = __ldg(g_adj + i);
        uint4 v = __ldg(hs + (size_t)s * 8 + l);
        acc8(acc, v);
    }

    // merge quarters: xor 8 then xor 16
#pragma unroll
    for (int k = 0; k < 8; k++)
        acc[k] += __shfl_xor_sync(0xffffffffu, acc[k], 8);
#pragma unroll
    for (int k = 0; k < 8; k++)
        acc[k] += __shfl_xor_sync(0xffffffffu, acc[k], 16);

    if (q == 0) {
        float di = __ldg(&g_dinv[gh]);
        float4 bv0 = __ldg((const float4*)b2 + l * 2);
        float4 bv1 = __ldg((const float4*)b2 + l * 2 + 1);
        float* op = out + (size_t)gh * RPR + l * 8;
        *(float4*)(op) = make_float4(fmaf(di, acc[0], bv0.x), fmaf(di, acc[1], bv0.y),
                                     fmaf(di, acc[2], bv0.z), fmaf(di, acc[3], bv0.w));
        *(float4*)(op + 4) = make_float4(fmaf(di, acc[4], bv1.x), fmaf(di, acc[5], bv1.y),
                                         fmaf(di, acc[6], bv1.z), fmaf(di, acc[7], bv1.w));
    }
}

// ---------------- launch ----------------
#define SMEM_GEMM1 (2 * 128 * LDA1 * 2)                 // 69632 B
#define SMEM_GEMM2 (128 * LDA2 * 2 + 128 * LDB2 * 2)    // 53248 B

extern "C" void kernel_launch(void* const* d_in, const int* in_sizes, int n_in,
                              void* d_out, int out_size) {
    const int*   edge = (const int*)d_in[0];     // [2, E]: src row, dst row
    const float* x    = (const float*)d_in[1];   // [N, 128]
    const float* W1   = (const float*)d_in[2];   // [128, 128]
    const float* b1   = (const float*)d_in[3];   // [128]
    const float* W2   = (const float*)d_in[4];   // [128, 64]
    const float* b2   = (const float*)d_in[5];   // [64]
    float* out = (float*)d_out;                  // [N, 64]

    const int* src = edge;
    const int* dst = edge + N_EDGES;

    cudaFuncSetAttribute(k_gemm1_tc, cudaFuncAttributeMaxDynamicSharedMemorySize,
                         SMEM_GEMM1);
    cudaFuncSetAttribute(k_gemm2_tc, cudaFuncAttributeMaxDynamicSharedMemorySize,
                         SMEM_GEMM2);

    // CSR build (+ degree/dinv); fill is atomic-free (rank captured in hist)
    k_zero<<<SCAN_BLOCKS, 256>>>();
    k_hist<<<2048, 256>>>(dst);
    k_scan<<<SCAN_BLOCKS, 256>>>();
    k_fill<<<2048, 256>>>(src, dst);

    // layer 1
    k_gemm1_tc<<<(N_NODES + 127) / 128, 256, SMEM_GEMM1>>>(x, W1);
    k_agg1<<<(N_NODES * 32 + 255) / 256, 256>>>(b1);

    // layer 2
    k_gemm2_tc<<<(N_NODES + 127) / 128, 256, SMEM_GEMM2>>>(W2);
    k_agg2<<<(N_NODES * 32 + 255) / 256, 256>>>(b2, out);
}